// round 2
// baseline (speedup 1.0000x reference)
#include <cuda_runtime.h>

// GaussianUpsampling: out[b,c,f] = sum_j softmax_j(-0.1*(f - c_j)^2) * x[b,c,j]
//   c = cumsum(w) - 0.5*w   (bit-matches JAX associative_scan Brent-Kung tree)
// B=16, C=256, T_text=512, T_feat=4096. Masks are structurally all-true.
//
// Banded algorithm: weights beyond |t - c_j| > 18 are < 1e-14 relative.
// Bands precomputed per 64-frame tile in the scan kernel (4-aligned jlo).
// Gauss kernel: single-pass whole-band tile (cap 64 tokens), XOR-swizzled
// smem x tile for conflict-free STS/LDS with coalesced global loads.

#define NB 16
#define NC 256
#define TT 512
#define TFEAT 4096
#define DELTA_F 0.1f
#define TILE_F 64
#define NTILES (TFEAT / TILE_F)   // 64
#define MAXBAND 64
#define NTHREADS 256

__device__ float g_c[NB * TT];
__device__ int2  g_band[NB * NTILES];

__device__ __forceinline__ int lower_bound_s(const float* c, float v) {
  int lo = 0, hi = TT;
  while (lo < hi) { int m = (lo + hi) >> 1; if (c[m] < v) lo = m + 1; else hi = m; }
  return lo;
}

// ---------------------------------------------------------------------------
// Brent-Kung scan replicating jax.lax.associative_scan's exact add tree,
// then per-tile band computation (one thread per 64-frame tile).
// ---------------------------------------------------------------------------
__global__ void cumsum_kernel(const float* __restrict__ w) {
  __shared__ float buf[1024];
  __shared__ float c_sh[TT];
  const int b = blockIdx.x;
  const int tid = threadIdx.x;
  const float* wb = w + b * TT;

  for (int i = tid; i < TT; i += blockDim.x) buf[i] = wb[i];
  __syncthreads();

  for (int size = TT; size > 1; size >>= 1) {   // up-sweep
    int off = 1024 - 2 * size, noff = 1024 - size, half = size >> 1;
    for (int i = tid; i < half; i += blockDim.x)
      buf[noff + i] = buf[off + 2 * i] + buf[off + 2 * i + 1];
    __syncthreads();
  }
  for (int size = 2; size <= TT; size <<= 1) {  // down-sweep
    int off = 1024 - 2 * size, offp = 1024 - size, half = size >> 1;
    for (int i = tid; i < half; i += blockDim.x) {
      float sp = buf[offp + i];
      if (2 * i + 2 < size) {
        float t = sp + buf[off + 2 * i + 2];
        buf[off + 2 * i + 1] = sp;
        buf[off + 2 * i + 2] = t;
      } else {
        buf[off + 2 * i + 1] = sp;
      }
    }
    __syncthreads();
  }
  for (int i = tid; i < TT; i += blockDim.x) {
    float cv = buf[i] - 0.5f * wb[i];
    c_sh[i] = cv;
    g_c[b * TT + i] = cv;
  }
  __syncthreads();

  if (tid < NTILES) {
    const float R = 18.0f;  // exp(-0.1*18^2) ~ 8e-15 relative
    float tmin = (float)(tid * TILE_F);
    float tmax = tmin + (float)(TILE_F - 1);
    int jlo = lower_bound_s(c_sh, tmin - R);
    int jhi = lower_bound_s(c_sh, tmax + R);
    int plo = lower_bound_s(c_sh, tmin);
    int phi = lower_bound_s(c_sh, tmax);
    jlo = min(jlo, max(plo - 1, 0));          // always include nearest tokens
    jhi = max(jhi, min(phi + 1, TT));
    jlo &= ~3;                                 // float4 alignment of band start
    if (jhi - jlo > MAXBAND) {                 // (statistically impossible) cap
      int slack = (max(0, (plo - 1) - jlo)) & ~3;
      int need  = jhi - jlo - MAXBAND;
      int adv   = min((need + 3) & ~3, slack);
      jlo += adv;
      jhi = min(jhi, jlo + MAXBAND);
    }
    g_band[b * NTILES + tid] = make_int2(jlo, jhi);
  }
}

// ---------------------------------------------------------------------------
// Fused banded softmax + GEMM. Block = (64-frame tile, batch). 256 threads.
// Thread tile: 4 channels x 16 frames. Whole band resident in smem.
// ---------------------------------------------------------------------------
__global__ __launch_bounds__(NTHREADS, 2) void gauss_kernel(
    const float* __restrict__ x, float* __restrict__ out)
{
  extern __shared__ float sm[];
  float* x_s    = sm;                                // [MAXBAND][NC] swizzled
  float* attn_s = sm + MAXBAND * NC;                 // [MAXBAND][TILE_F]
  float* c_b    = attn_s + MAXBAND * TILE_F;         // [MAXBAND]
  float* m_s    = c_b + MAXBAND;                     // [TILE_F]
  float* r_s    = m_s + TILE_F;                      // [TILE_F]

  const int b   = blockIdx.y;
  const int f0  = blockIdx.x * TILE_F;
  const int tid = threadIdx.x;

  const int2 bd = g_band[b * NTILES + blockIdx.x];
  const int jlo = bd.x, jhi = bd.y;
  const int nband = jhi - jlo;

  if (tid < MAXBAND && tid < nband) c_b[tid] = g_c[b * TT + jlo + tid];

  // ---- coalesced x load + swizzled STS --------------------------------
  // thread: channel c = cl + 4*rep + 16*p, token quad tq (4 tokens).
  // warp covers 4 channel rows x 128B contiguous => ~4 lines per LDG.
  {
    const int cl  = tid & 3;
    const int tq  = (tid >> 2) & 15;
    const int rep = tid >> 6;
    const int row0 = 4 * tq;
    if (row0 < nband) {
      const bool full = (row0 + 4 <= nband);
      const float* xb = x + (size_t)b * NC * TT + jlo + row0;
      #pragma unroll
      for (int p = 0; p < 16; p++) {
        const int c = cl + 4 * rep + 16 * p;
        const float* src = xb + (size_t)c * TT;
        float v[4];
        if (full) {
          float4 t4 = *(const float4*)src;
          v[0] = t4.x; v[1] = t4.y; v[2] = t4.z; v[3] = t4.w;
        } else {
          v[0] = src[0];
          v[1] = (row0 + 1 < nband) ? src[1] : 0.0f;
          v[2] = (row0 + 2 < nband) ? src[2] : 0.0f;
          v[3] = (row0 + 3 < nband) ? src[3] : 0.0f;
        }
        const int cq  = c >> 2;                  // = rep + 4p
        const int col = 4 * (cq ^ tq) + cl;      // XOR swizzle: STS conflict-free
        #pragma unroll
        for (int r = 0; r < 4; r++) x_s[(row0 + r) * NC + col] = v[r];
      }
    }
  }
  __syncthreads();

  // ---- per-frame softmax stats (4 threads per frame) ------------------
  {
    const int f = tid >> 2, l4 = tid & 3;
    const float tf = (float)(f0 + f);
    float m = -1e30f;
    for (int kk = l4; kk < nband; kk += 4) {
      float d = tf - c_b[kk];
      m = fmaxf(m, -DELTA_F * (d * d));
    }
    m = fmaxf(m, __shfl_xor_sync(0xffffffffu, m, 1));
    m = fmaxf(m, __shfl_xor_sync(0xffffffffu, m, 2));
    float s = 0.0f;
    for (int kk = l4; kk < nband; kk += 4) {
      float d = tf - c_b[kk];
      s += __expf(-DELTA_F * (d * d) - m);
    }
    s += __shfl_xor_sync(0xffffffffu, s, 1);
    s += __shfl_xor_sync(0xffffffffu, s, 2);
    if (l4 == 0) { m_s[f] = m; r_s[f] = 1.0f / s; }
  }
  __syncthreads();

  // ---- normalized attention tile --------------------------------------
  {
    const int iters = (nband * TILE_F + NTHREADS - 1) >> 8;
    for (int i = 0; i < iters; i++) {
      int idx = tid + (i << 8);
      int kk = idx >> 6, f = idx & 63;
      if (kk < nband) {
        float d = (float)(f0 + f) - c_b[kk];
        attn_s[kk * TILE_F + f] = __expf(-DELTA_F * (d * d) - m_s[f]) * r_s[f];
      }
    }
  }
  __syncthreads();

  // ---- main FMA loop ---------------------------------------------------
  const int c_id = tid >> 2;            // channel group 0..63 (4 channels)
  const int fg   = (tid & 3) << 4;      // frame group base (16 frames)

  float acc[4][16];
  #pragma unroll
  for (int ci = 0; ci < 4; ci++)
    #pragma unroll
    for (int fi = 0; fi < 16; fi++) acc[ci][fi] = 0.0f;

  #pragma unroll 2
  for (int kk = 0; kk < nband; kk++) {
    const int cpos = c_id ^ (kk >> 2);
    float4 xv = *(const float4*)&x_s[kk * NC + 4 * cpos];
    const float* ar = &attn_s[kk * TILE_F + fg];
    float4 a0 = *(const float4*)(ar);
    float4 a1 = *(const float4*)(ar + 4);
    float4 a2 = *(const float4*)(ar + 8);
    float4 a3 = *(const float4*)(ar + 12);
    float xc[4] = {xv.x, xv.y, xv.z, xv.w};
    float av[16] = {a0.x, a0.y, a0.z, a0.w, a1.x, a1.y, a1.z, a1.w,
                    a2.x, a2.y, a2.z, a2.w, a3.x, a3.y, a3.z, a3.w};
    #pragma unroll
    for (int ci = 0; ci < 4; ci++)
      #pragma unroll
      for (int fi = 0; fi < 16; fi++)
        acc[ci][fi] = fmaf(xc[ci], av[fi], acc[ci][fi]);
  }

  // ---- store -----------------------------------------------------------
  #pragma unroll
  for (int ci = 0; ci < 4; ci++) {
    float* o = out + ((size_t)b * NC + 4 * c_id + ci) * TFEAT + f0 + fg;
    #pragma unroll
    for (int qi = 0; qi < 4; qi++)
      *(float4*)&o[4 * qi] = make_float4(acc[ci][4 * qi], acc[ci][4 * qi + 1],
                                         acc[ci][4 * qi + 2], acc[ci][4 * qi + 3]);
  }
}

extern "C" void kernel_launch(void* const* d_in, const int* in_sizes, int n_in,
                              void* d_out, int out_size) {
  const float* x = (const float*)d_in[0];   // (B, C, T_text) fp32
  const float* w = (const float*)d_in[1];   // (B, T_text)    fp32
  float* out = (float*)d_out;               // (B, C, T_feat) fp32

  const int smem_b = (MAXBAND * NC + MAXBAND * TILE_F + MAXBAND + 2 * TILE_F) * 4;
  cudaFuncSetAttribute(gauss_kernel, cudaFuncAttributeMaxDynamicSharedMemorySize, smem_b);

  cumsum_kernel<<<NB, 256>>>(w);
  gauss_kernel<<<dim3(NTILES, NB), NTHREADS, smem_b>>>(x, out);
}

// round 3
// speedup vs baseline: 1.2532x; 1.2532x over previous
#include <cuda_runtime.h>

// GaussianUpsampling: out[b,c,f] = sum_j softmax_j(-0.1*(f - c_j)^2) * x[b,c,j]
//   c = cumsum(w) - 0.5*w   (bit-matches JAX associative_scan Brent-Kung tree)
// B=16, C=256, T_text=512, T_feat=4096. Masks structurally all-true.
//
// Banded: weights beyond |t - c_j| > 18 are < 1e-14 relative. Bands
// precomputed per 32-frame tile (4-aligned jlo, capped at 32 tokens).
// Gauss kernel: 2048 small CTAs, coalesced float4 token loads with XOR-
// swizzled smem transpose, warp-local stores (8 lines/STG), acc 4ch x 8fr.

#define NB 16
#define NC 256
#define TT 512
#define TFEAT 4096
#define DELTA_F 0.1f
#define TILE_F 32
#define NTILES (TFEAT / TILE_F)   // 128
#define MAXBAND 32
#define NTHREADS 256

__device__ float g_c[NB * TT];
__device__ int2  g_band[NB * NTILES];

__device__ __forceinline__ int lower_bound_s(const float* c, float v) {
  int lo = 0, hi = TT;
  while (lo < hi) { int m = (lo + hi) >> 1; if (c[m] < v) lo = m + 1; else hi = m; }
  return lo;
}

// ---------------------------------------------------------------------------
// Brent-Kung scan replicating jax.lax.associative_scan's exact add tree,
// then per-tile band computation (one thread per 32-frame tile).
// ---------------------------------------------------------------------------
__global__ void cumsum_kernel(const float* __restrict__ w) {
  __shared__ float buf[1024];
  __shared__ float c_sh[TT];
  const int b = blockIdx.x;
  const int tid = threadIdx.x;
  const float* wb = w + b * TT;

  for (int i = tid; i < TT; i += blockDim.x) buf[i] = wb[i];
  __syncthreads();

  for (int size = TT; size > 1; size >>= 1) {   // up-sweep
    int off = 1024 - 2 * size, noff = 1024 - size, half = size >> 1;
    for (int i = tid; i < half; i += blockDim.x)
      buf[noff + i] = buf[off + 2 * i] + buf[off + 2 * i + 1];
    __syncthreads();
  }
  for (int size = 2; size <= TT; size <<= 1) {  // down-sweep
    int off = 1024 - 2 * size, offp = 1024 - size, half = size >> 1;
    for (int i = tid; i < half; i += blockDim.x) {
      float sp = buf[offp + i];
      if (2 * i + 2 < size) {
        float t = sp + buf[off + 2 * i + 2];
        buf[off + 2 * i + 1] = sp;
        buf[off + 2 * i + 2] = t;
      } else {
        buf[off + 2 * i + 1] = sp;
      }
    }
    __syncthreads();
  }
  for (int i = tid; i < TT; i += blockDim.x) {
    float cv = buf[i] - 0.5f * wb[i];
    c_sh[i] = cv;
    g_c[b * TT + i] = cv;
  }
  __syncthreads();

  for (int t = tid; t < NTILES; t += blockDim.x) {
    const float R = 18.0f;  // exp(-0.1*18^2) ~ 8e-15 relative
    float tmin = (float)(t * TILE_F);
    float tmax = tmin + (float)(TILE_F - 1);
    int jlo = lower_bound_s(c_sh, tmin - R);
    int jhi = lower_bound_s(c_sh, tmax + R);
    int plo = lower_bound_s(c_sh, tmin);
    int phi = lower_bound_s(c_sh, tmax);
    jlo = min(jlo, max(plo - 1, 0));          // always include nearest tokens
    jhi = max(jhi, min(phi + 1, TT));
    jlo &= ~3;                                 // float4 alignment
    if (jhi - jlo > MAXBAND) {                 // statistically impossible cap
      int slack = (max(0, (plo - 1) - jlo)) & ~3;
      int need  = jhi - jlo - MAXBAND;
      int adv   = min((need + 3) & ~3, slack);
      jlo += adv;
      jhi = min(jhi, jlo + MAXBAND);
    }
    g_band[b * NTILES + t] = make_int2(jlo, jhi);
  }
}

// ---------------------------------------------------------------------------
// Fused banded softmax + GEMM. Block = (32-frame tile, batch). 256 threads.
// Thread tile: 4 channels x 8 frames.
// ---------------------------------------------------------------------------
__global__ __launch_bounds__(NTHREADS, 3) void gauss_kernel(
    const float* __restrict__ x, float* __restrict__ out)
{
  __shared__ float x_s[MAXBAND][NC];         // XOR-swizzled token-major tile
  __shared__ float attn_s[MAXBAND][TILE_F];
  __shared__ float m_s[TILE_F];
  __shared__ float r_s[TILE_F];

  const int b   = blockIdx.y;
  const int f0  = blockIdx.x * TILE_F;
  const int tid = threadIdx.x;

  const int2 bd = g_band[b * NTILES + blockIdx.x];
  const int jlo = bd.x;
  const int nband  = bd.y - jlo;
  const int nband4 = (nband + 3) & ~3;
  const float* cb = g_c + b * TT + jlo;

  // ---- coalesced x load + swizzled STS (no cross-thread dependency) ----
  // lane: cl = channel low bits, tq = token quad; warp = 4 ch rows x 128B.
  // STS bank = (4*(cq^tq)+cl) mod 32 -> all 32 lanes distinct: conflict-free.
  {
    const int cl  = tid & 3;
    const int tq  = (tid >> 2) & 7;
    const int rep = tid >> 5;
    const int row0 = 4 * tq;
    if (row0 < nband4) {
      const bool full = (row0 + 4 <= nband);
      const float* xb = x + (size_t)b * NC * TT + jlo + row0;
      #pragma unroll
      for (int p = 0; p < 8; p++) {
        const int c = cl + 4 * rep + 32 * p;
        const float* src = xb + (size_t)c * TT;
        float v[4];
        if (full) {
          float4 t4 = *(const float4*)src;
          v[0] = t4.x; v[1] = t4.y; v[2] = t4.z; v[3] = t4.w;
        } else {
          v[0] = (row0     < nband) ? src[0] : 0.0f;
          v[1] = (row0 + 1 < nband) ? src[1] : 0.0f;
          v[2] = (row0 + 2 < nband) ? src[2] : 0.0f;
          v[3] = (row0 + 3 < nband) ? src[3] : 0.0f;
        }
        const int cq  = rep + 8 * p;
        const int col = 4 * (cq ^ tq) + cl;
        #pragma unroll
        for (int r = 0; r < 4; r++) x_s[row0 + r][col] = v[r];
      }
    }
  }

  // ---- per-frame softmax stats (8 threads/frame, reads g_c via L1) ----
  {
    const int f = tid >> 3, l8 = tid & 7;
    const float tf = (float)(f0 + f);
    float m = -1e30f;
    for (int kk = l8; kk < nband; kk += 8) {
      float d = tf - cb[kk];
      m = fmaxf(m, -DELTA_F * (d * d));
    }
    m = fmaxf(m, __shfl_xor_sync(0xffffffffu, m, 1));
    m = fmaxf(m, __shfl_xor_sync(0xffffffffu, m, 2));
    m = fmaxf(m, __shfl_xor_sync(0xffffffffu, m, 4));
    float s = 0.0f;
    for (int kk = l8; kk < nband; kk += 8) {
      float d = tf - cb[kk];
      s += __expf(-DELTA_F * (d * d) - m);
    }
    s += __shfl_xor_sync(0xffffffffu, s, 1);
    s += __shfl_xor_sync(0xffffffffu, s, 2);
    s += __shfl_xor_sync(0xffffffffu, s, 4);
    if (l8 == 0) { m_s[f] = m; r_s[f] = 1.0f / s; }
  }
  __syncthreads();

  // ---- normalized attention tile (pad rows zeroed) --------------------
  {
    const int total = nband4 * TILE_F;
    for (int idx = tid; idx < total; idx += NTHREADS) {
      int kk = idx >> 5, f = idx & 31;
      float a = 0.0f;
      if (kk < nband) {
        float d = (float)(f0 + f) - cb[kk];
        a = __expf(-DELTA_F * (d * d) - m_s[f]) * r_s[f];
      }
      attn_s[kk][f] = a;
    }
  }
  __syncthreads();

  // ---- main FMA loop ---------------------------------------------------
  const int cgrp = tid >> 2;           // 0..63: channels 4*cgrp..+3
  const int fg   = (tid & 3) << 3;     // frame base (8 frames)

  float acc[4][8];
  #pragma unroll
  for (int ci = 0; ci < 4; ci++)
    #pragma unroll
    for (int fi = 0; fi < 8; fi++) acc[ci][fi] = 0.0f;

  for (int kk0 = 0; kk0 < nband4; kk0 += 4) {
    const int cpos = 4 * (cgrp ^ (kk0 >> 2));
    #pragma unroll
    for (int u = 0; u < 4; u++) {
      const int kk = kk0 + u;
      float4 xv = *(const float4*)&x_s[kk][cpos];
      float4 a0 = *(const float4*)&attn_s[kk][fg];
      float4 a1 = *(const float4*)&attn_s[kk][fg + 4];
      float xc[4] = {xv.x, xv.y, xv.z, xv.w};
      float av[8] = {a0.x, a0.y, a0.z, a0.w, a1.x, a1.y, a1.z, a1.w};
      #pragma unroll
      for (int ci = 0; ci < 4; ci++)
        #pragma unroll
        for (int fi = 0; fi < 8; fi++)
          acc[ci][fi] = fmaf(xc[ci], av[fi], acc[ci][fi]);
    }
  }

  // ---- store: warp = 8 channel rows x 32 contiguous frames ------------
  #pragma unroll
  for (int ci = 0; ci < 4; ci++) {
    float* o = out + ((size_t)b * NC + 4 * cgrp + ci) * TFEAT + f0 + fg;
    *(float4*)&o[0] = make_float4(acc[ci][0], acc[ci][1], acc[ci][2], acc[ci][3]);
    *(float4*)&o[4] = make_float4(acc[ci][4], acc[ci][5], acc[ci][6], acc[ci][7]);
  }
}

extern "C" void kernel_launch(void* const* d_in, const int* in_sizes, int n_in,
                              void* d_out, int out_size) {
  const float* x = (const float*)d_in[0];   // (B, C, T_text) fp32
  const float* w = (const float*)d_in[1];   // (B, T_text)    fp32
  float* out = (float*)d_out;               // (B, C, T_feat) fp32

  cumsum_kernel<<<NB, 256>>>(w);
  gauss_kernel<<<dim3(NTILES, NB), NTHREADS>>>(x, out);
}

// round 4
// speedup vs baseline: 1.2616x; 1.0067x over previous
#include <cuda_runtime.h>

// GaussianUpsampling: out[b,c,f] = sum_j softmax_j(-0.1*(f - c_j)^2) * x[b,c,j]
//   c = cumsum(w) - 0.5*w   (bit-matches JAX associative_scan Brent-Kung tree)
// B=16, C=256, T_text=512, T_feat=4096. Masks structurally all-true.
//
// Banded: weights beyond |t - c_j| > 18 are < 1e-14 relative. Bands
// precomputed per 32-frame tile (4-aligned jlo, capped at 32 tokens).
// R4: main loop uses packed fma.rn.f32x2 (FFMA2) -> half the FMA instrs,
// bit-identical rounding vs scalar fmaf.

#define NB 16
#define NC 256
#define TT 512
#define TFEAT 4096
#define DELTA_F 0.1f
#define TILE_F 32
#define NTILES (TFEAT / TILE_F)   // 128
#define MAXBAND 32
#define NTHREADS 256

__device__ float g_c[NB * TT];
__device__ int2  g_band[NB * NTILES];

#define FMA2(acc, a, b) \
  asm("fma.rn.f32x2 %0, %1, %2, %0;" : "+l"(acc) : "l"(a), "l"(b))
#define PACK2(out, lo, hi) \
  asm("mov.b64 %0, {%1, %2};" : "=l"(out) : "f"(lo), "f"(hi))
#define UNPACK2(lo, hi, in) \
  asm("mov.b64 {%0, %1}, %2;" : "=f"(lo), "=f"(hi) : "l"(in))

__device__ __forceinline__ int lower_bound_s(const float* c, float v) {
  int lo = 0, hi = TT;
  while (lo < hi) { int m = (lo + hi) >> 1; if (c[m] < v) lo = m + 1; else hi = m; }
  return lo;
}

// ---------------------------------------------------------------------------
// Brent-Kung scan replicating jax.lax.associative_scan's exact add tree,
// then per-tile band computation.
// ---------------------------------------------------------------------------
__global__ void cumsum_kernel(const float* __restrict__ w) {
  __shared__ float buf[1024];
  __shared__ float c_sh[TT];
  const int b = blockIdx.x;
  const int tid = threadIdx.x;
  const float* wb = w + b * TT;

  for (int i = tid; i < TT; i += blockDim.x) buf[i] = wb[i];
  __syncthreads();

  for (int size = TT; size > 1; size >>= 1) {   // up-sweep
    int off = 1024 - 2 * size, noff = 1024 - size, half = size >> 1;
    for (int i = tid; i < half; i += blockDim.x)
      buf[noff + i] = buf[off + 2 * i] + buf[off + 2 * i + 1];
    __syncthreads();
  }
  for (int size = 2; size <= TT; size <<= 1) {  // down-sweep
    int off = 1024 - 2 * size, offp = 1024 - size, half = size >> 1;
    for (int i = tid; i < half; i += blockDim.x) {
      float sp = buf[offp + i];
      if (2 * i + 2 < size) {
        float t = sp + buf[off + 2 * i + 2];
        buf[off + 2 * i + 1] = sp;
        buf[off + 2 * i + 2] = t;
      } else {
        buf[off + 2 * i + 1] = sp;
      }
    }
    __syncthreads();
  }
  for (int i = tid; i < TT; i += blockDim.x) {
    float cv = buf[i] - 0.5f * wb[i];
    c_sh[i] = cv;
    g_c[b * TT + i] = cv;
  }
  __syncthreads();

  for (int t = tid; t < NTILES; t += blockDim.x) {
    const float R = 18.0f;  // exp(-0.1*18^2) ~ 8e-15 relative
    float tmin = (float)(t * TILE_F);
    float tmax = tmin + (float)(TILE_F - 1);
    int jlo = lower_bound_s(c_sh, tmin - R);
    int jhi = lower_bound_s(c_sh, tmax + R);
    int plo = lower_bound_s(c_sh, tmin);
    int phi = lower_bound_s(c_sh, tmax);
    jlo = min(jlo, max(plo - 1, 0));          // always include nearest tokens
    jhi = max(jhi, min(phi + 1, TT));
    jlo &= ~3;                                 // float4 alignment
    if (jhi - jlo > MAXBAND) {                 // statistically impossible cap
      int slack = (max(0, (plo - 1) - jlo)) & ~3;
      int need  = jhi - jlo - MAXBAND;
      int adv   = min((need + 3) & ~3, slack);
      jlo += adv;
      jhi = min(jhi, jlo + MAXBAND);
    }
    g_band[b * NTILES + t] = make_int2(jlo, jhi);
  }
}

// ---------------------------------------------------------------------------
// Fused banded softmax + GEMM. Block = (32-frame tile, batch). 256 threads.
// Thread tile: 4 channels x 8 frames (4 f32x2 accumulator pairs per channel).
// ---------------------------------------------------------------------------
__global__ __launch_bounds__(NTHREADS, 3) void gauss_kernel(
    const float* __restrict__ x, float* __restrict__ out)
{
  __shared__ __align__(16) float x_s[MAXBAND][NC];       // XOR-swizzled
  __shared__ __align__(16) float attn_s[MAXBAND][TILE_F];
  __shared__ float m_s[TILE_F];
  __shared__ float r_s[TILE_F];

  const int b   = blockIdx.y;
  const int f0  = blockIdx.x * TILE_F;
  const int tid = threadIdx.x;

  const int2 bd = g_band[b * NTILES + blockIdx.x];
  const int jlo = bd.x;
  const int nband  = bd.y - jlo;
  const int nband4 = (nband + 3) & ~3;
  const float* cb = g_c + b * TT + jlo;

  // ---- coalesced x load + swizzled STS --------------------------------
  // lane: cl = channel low bits, tq = token quad; warp = 4 ch rows x 128B.
  // STS bank = (4*(cq^tq)+cl) mod 32 -> all lanes distinct: conflict-free.
  {
    const int cl  = tid & 3;
    const int tq  = (tid >> 2) & 7;
    const int rep = tid >> 5;
    const int row0 = 4 * tq;
    if (row0 < nband4) {
      const bool full = (row0 + 4 <= nband);
      const float* xb = x + (size_t)b * NC * TT + jlo + row0;
      #pragma unroll
      for (int p = 0; p < 8; p++) {
        const int c = cl + 4 * rep + 32 * p;
        const float* src = xb + (size_t)c * TT;
        float v[4];
        if (full) {
          float4 t4 = *(const float4*)src;
          v[0] = t4.x; v[1] = t4.y; v[2] = t4.z; v[3] = t4.w;
        } else {
          v[0] = (row0     < nband) ? src[0] : 0.0f;
          v[1] = (row0 + 1 < nband) ? src[1] : 0.0f;
          v[2] = (row0 + 2 < nband) ? src[2] : 0.0f;
          v[3] = (row0 + 3 < nband) ? src[3] : 0.0f;
        }
        const int cq  = rep + 8 * p;
        const int col = 4 * (cq ^ tq) + cl;
        #pragma unroll
        for (int r = 0; r < 4; r++) x_s[row0 + r][col] = v[r];
      }
    }
  }

  // ---- per-frame softmax stats (8 threads/frame) ----------------------
  {
    const int f = tid >> 3, l8 = tid & 7;
    const float tf = (float)(f0 + f);
    float m = -1e30f;
    for (int kk = l8; kk < nband; kk += 8) {
      float d = tf - cb[kk];
      m = fmaxf(m, -DELTA_F * (d * d));
    }
    m = fmaxf(m, __shfl_xor_sync(0xffffffffu, m, 1));
    m = fmaxf(m, __shfl_xor_sync(0xffffffffu, m, 2));
    m = fmaxf(m, __shfl_xor_sync(0xffffffffu, m, 4));
    float s = 0.0f;
    for (int kk = l8; kk < nband; kk += 8) {
      float d = tf - cb[kk];
      s += __expf(-DELTA_F * (d * d) - m);
    }
    s += __shfl_xor_sync(0xffffffffu, s, 1);
    s += __shfl_xor_sync(0xffffffffu, s, 2);
    s += __shfl_xor_sync(0xffffffffu, s, 4);
    if (l8 == 0) { m_s[f] = m; r_s[f] = 1.0f / s; }
  }
  __syncthreads();

  // ---- normalized attention tile (pad rows zeroed) --------------------
  {
    const int total = nband4 * TILE_F;
    for (int idx = tid; idx < total; idx += NTHREADS) {
      int kk = idx >> 5, f = idx & 31;
      float a = 0.0f;
      if (kk < nband) {
        float d = (float)(f0 + f) - cb[kk];
        a = __expf(-DELTA_F * (d * d) - m_s[f]) * r_s[f];
      }
      attn_s[kk][f] = a;
    }
  }
  __syncthreads();

  // ---- main FMA loop: packed f32x2 -------------------------------------
  const int cgrp = tid >> 2;           // 0..63: channels 4*cgrp..+3
  const int fg   = (tid & 3) << 3;     // frame base (8 frames)

  unsigned long long acc2[4][4];       // [channel][frame-pair]
  #pragma unroll
  for (int ci = 0; ci < 4; ci++)
    #pragma unroll
    for (int q = 0; q < 4; q++) acc2[ci][q] = 0ull;

  for (int kk0 = 0; kk0 < nband4; kk0 += 4) {
    const int cpos = 4 * (cgrp ^ (kk0 >> 2));
    #pragma unroll
    for (int u = 0; u < 4; u++) {
      const int kk = kk0 + u;
      float4 xv = *(const float4*)&x_s[kk][cpos];
      ulonglong2 a01 = *(const ulonglong2*)&attn_s[kk][fg];       // (f0,f1),(f2,f3)
      ulonglong2 a23 = *(const ulonglong2*)&attn_s[kk][fg + 4];   // (f4,f5),(f6,f7)
      unsigned long long ap[4] = {a01.x, a01.y, a23.x, a23.y};
      float xc[4] = {xv.x, xv.y, xv.z, xv.w};
      unsigned long long xp[4];
      #pragma unroll
      for (int ci = 0; ci < 4; ci++) PACK2(xp[ci], xc[ci], xc[ci]);
      #pragma unroll
      for (int ci = 0; ci < 4; ci++)
        #pragma unroll
        for (int q = 0; q < 4; q++)
          FMA2(acc2[ci][q], xp[ci], ap[q]);
    }
  }

  // ---- store: warp = 8 channel rows x 32 contiguous frames ------------
  #pragma unroll
  for (int ci = 0; ci < 4; ci++) {
    float r[8];
    #pragma unroll
    for (int q = 0; q < 4; q++) UNPACK2(r[2 * q], r[2 * q + 1], acc2[ci][q]);
    float* o = out + ((size_t)b * NC + 4 * cgrp + ci) * TFEAT + f0 + fg;
    *(float4*)&o[0] = make_float4(r[0], r[1], r[2], r[3]);
    *(float4*)&o[4] = make_float4(r[4], r[5], r[6], r[7]);
  }
}

extern "C" void kernel_launch(void* const* d_in, const int* in_sizes, int n_in,
                              void* d_out, int out_size) {
  const float* x = (const float*)d_in[0];   // (B, C, T_text) fp32
  const float* w = (const float*)d_in[1];   // (B, T_text)    fp32
  float* out = (float*)d_out;               // (B, C, T_feat) fp32

  cumsum_kernel<<<NB, 256>>>(w);
  gauss_kernel<<<dim3(NTILES, NB), NTHREADS>>>(x, out);
}